// round 13
// baseline (speedup 1.0000x reference)
#include <cuda_runtime.h>
#include <cuda_fp16.h>
#include <cstdint>

// Problem constants
constexpr int BB = 256;     // batch
constexpr int H  = 1024;    // hidden
constexpr int L  = 10000;   // labels
constexpr int MT = 128;     // M per CTA
constexpr int LPB = 16;     // labels per CTA (N = 128)
constexpr int KC = 64;      // K per chunk
constexpr int NCHUNK = H / KC;  // 16
constexpr int NSTAGE_A = 3;

// smem: A 3 stages x 16KB, B 2 bufs x 16KB
constexpr int OFF_A = 0;
constexpr int A_STAGE = 16384;
constexpr int OFF_B = NSTAGE_A * A_STAGE;       // 49152
constexpr int B_BUF = 16384;
constexpr int SMEM_DYN = 1024 + OFF_B + 2 * B_BUF;   // 82944

// pre-converted fp16 embeddings [256][1024]
__device__ __align__(16) __half g_eA[BB * H];

// ---------------- helpers ----------------
__device__ __forceinline__ uint32_t smem_u32(const void* p) {
    uint32_t a;
    asm("{ .reg .u64 t; cvta.to.shared.u64 t, %1; cvt.u32.u64 %0, t; }" : "=r"(a) : "l"(p));
    return a;
}
__device__ __forceinline__ void cpasync16(uint32_t dst, const void* src) {
    asm volatile("cp.async.cg.shared.global [%0], [%1], 16;" :: "r"(dst), "l"(src));
}
#define CP_COMMIT() asm volatile("cp.async.commit_group;" ::: "memory")
#define CP_WAIT1()  asm volatile("cp.async.wait_group 1;" ::: "memory")
#define CP_WAIT0()  asm volatile("cp.async.wait_group 0;" ::: "memory")

__device__ __forceinline__ void prefetchL2(const void* p) {
    asm volatile("prefetch.global.L2 [%0];" :: "l"(p));
}
__device__ __forceinline__ void ldsm4(uint32_t* r, uint32_t addr) {
    asm volatile("ldmatrix.sync.aligned.m8n8.x4.shared.b16 {%0,%1,%2,%3}, [%4];"
                 : "=r"(r[0]), "=r"(r[1]), "=r"(r[2]), "=r"(r[3]) : "r"(addr));
}
__device__ __forceinline__ void ldsm4t(uint32_t* r, uint32_t addr) {
    asm volatile("ldmatrix.sync.aligned.m8n8.x4.trans.shared.b16 {%0,%1,%2,%3}, [%4];"
                 : "=r"(r[0]), "=r"(r[1]), "=r"(r[2]), "=r"(r[3]) : "r"(addr));
}
__device__ __forceinline__ void mma16816(float* c, const uint32_t* a, const uint32_t* b) {
    asm volatile(
        "mma.sync.aligned.m16n8k16.row.col.f32.f16.f16.f32 "
        "{%0,%1,%2,%3}, {%4,%5,%6,%7}, {%8,%9}, {%0,%1,%2,%3};"
        : "+f"(c[0]), "+f"(c[1]), "+f"(c[2]), "+f"(c[3])
        : "r"(a[0]), "r"(a[1]), "r"(a[2]), "r"(a[3]), "r"(b[0]), "r"(b[1]));
}
__device__ __forceinline__ uint32_t pkh2(float x0, float x1) {
    __half2 h = __float22half2_rn(make_float2(x0, x1));
    return *reinterpret_cast<uint32_t*>(&h);
}

// ---------------- pre-kernel: emb fp32 -> fp16 ----------------
__global__ void cvt_emb_kernel(const float* __restrict__ emb) {
    int i = blockIdx.x * blockDim.x + threadIdx.x;   // 65536 float4s
    float4 v = reinterpret_cast<const float4*>(emb)[i];
    reinterpret_cast<uint2*>(g_eA)[i] = make_uint2(pkh2(v.x, v.y), pkh2(v.z, v.w));
}

// ---------------- main kernel ----------------
__global__ __launch_bounds__(256, 2)
void imec_hmma_kernel(const float* __restrict__ W1,
                      const float* __restrict__ b1,
                      const float* __restrict__ W2,
                      const float* __restrict__ b2,
                      float* __restrict__ out)
{
    extern __shared__ char smraw[];
    uint32_t sraw = smem_u32(smraw);
    uint32_t sb = (sraw + 1023u) & ~1023u;
    char* smc = smraw + (sb - sraw);

    const int tid  = threadIdx.x;
    const int lane = tid & 31;
    const int wid  = tid >> 5;        // 0..7
    const int wm   = wid & 1;         // warp M group: 64 rows each (2x64=128)
    const int wn   = wid >> 1;        // warp N group: 32 cols = 4 labels (4x32=128)

    const int lg = blockIdx.x >> 1;
    const int mt = blockIdx.x & 1;
    const int m0 = mt * MT;
    const int l0 = lg * LPB;

    // ---- A staging: thread -> (row, k-half), 128B swizzled rows ----
    const int ar = tid >> 1;          // 0..127
    const int ahalf = tid & 1;
    const char* aSrc = reinterpret_cast<const char*>(g_eA)
                     + (size_t)(m0 + ar) * (H * 2) + ahalf * 64;
    const uint32_t aDstBase = (uint32_t)(ar * 128);
    const uint32_t arx = (uint32_t)(ar & 7);

    // ---- B staging: warp owns 2 labels (2*wid, 2*wid+1); coalesced LDG.128 ----
    const float* bSrc0 = W1 + (size_t)(l0 + 2 * wid)     * (H * 8);
    const float* bSrc1 = W1 + (size_t)(l0 + 2 * wid + 1) * (H * 8);
    const uint32_t bDst0 = (uint32_t)((2 * wid)     * 1024) + (uint32_t)(lane * 8);
    const uint32_t bDst1 = (uint32_t)((2 * wid + 1) * 1024) + (uint32_t)(lane * 8);

    // ---- B L2-prefetch address: thread covers one 128B line of the CTA's
    //      32KB B chunk: label = tid/16, 128B-segment = tid%16 ----
    const float* pfBase = W1 + (size_t)(l0 + (tid >> 4)) * (H * 8) + (tid & 15) * 32;

    // ---- A fragment addresses (K-major, swizzled) ----
    uint32_t aOff[4], aXor[4];
#pragma unroll
    for (int mi = 0; mi < 4; ++mi) {
        int r = wm * 64 + mi * 16 + (lane & 15);
        aOff[mi] = (uint32_t)r * 128u;
        aXor[mi] = (uint32_t)(r & 7) << 4;
    }
    const uint32_t aKadd = (uint32_t)(lane >> 4) << 4;

    // ---- B fragment addresses (per-label 1KB MN-major blobs, trans ldsm) ----
    uint32_t bOff[2];
#pragma unroll
    for (int i = 0; i < 2; ++i)
        bOff[i] = (uint32_t)((wn * 4 + 2 * i + (lane >> 4)) * 1024 + (lane & 15) * 16);

    float acc[4][4][4];
#pragma unroll
    for (int mi = 0; mi < 4; ++mi)
#pragma unroll
        for (int ni = 0; ni < 4; ++ni)
#pragma unroll
            for (int k = 0; k < 4; ++k) acc[mi][ni][k] = 0.0f;

    float4 bv[4];   // B prefetch for ONE label (reused per half)

    auto stageA = [&](int c) {
        const uint32_t ad = sb + (uint32_t)(OFF_A + (c % NSTAGE_A) * A_STAGE) + aDstBase;
        const char* as = aSrc + c * 128;
#pragma unroll
        for (int j = 0; j < 4; ++j) {
            uint32_t u = (uint32_t)(ahalf * 4 + j);
            cpasync16(ad + ((u ^ arx) << 4), as + j * 16);
        }
    };

    auto ldgB = [&](int c, int h) {
        const float* s = (h == 0 ? bSrc0 : bSrc1) + (size_t)c * (KC * 8);
#pragma unroll
        for (int j = 0; j < 4; ++j)
            bv[j] = *reinterpret_cast<const float4*>(s + j * 128 + lane * 4);
    };

    auto stsB = [&](int c, int h) {
        char* bd = smc + OFF_B + (c & 1) * B_BUF + (h == 0 ? bDst0 : bDst1);
#pragma unroll
        for (int j = 0; j < 4; ++j) {
            uint2 w = make_uint2(pkh2(bv[j].x, bv[j].y), pkh2(bv[j].z, bv[j].w));
            *reinterpret_cast<uint2*>(bd + j * 256) = w;
        }
    };

    auto compute = [&](int c, int ks0, int ks1) {
        const uint32_t bA = sb + (uint32_t)(OFF_A + (c % NSTAGE_A) * A_STAGE);
        const uint32_t bB = sb + (uint32_t)(OFF_B + (c & 1) * B_BUF);
#pragma unroll
        for (int ks = ks0; ks < ks1; ++ks) {
            const uint32_t koff = (uint32_t)ks * 32u;
            uint32_t a[4][4], b[2][4];
#pragma unroll
            for (int mi = 0; mi < 4; ++mi)
                ldsm4(a[mi], bA + aOff[mi] + ((koff + aKadd) ^ aXor[mi]));
#pragma unroll
            for (int i = 0; i < 2; ++i)
                ldsm4t(b[i], bB + bOff[i] + (uint32_t)ks * 256u);
#pragma unroll
            for (int mi = 0; mi < 4; ++mi)
#pragma unroll
                for (int i = 0; i < 2; ++i) {
                    mma16816(acc[mi][2 * i],     a[mi], &b[i][0]);
                    mma16816(acc[mi][2 * i + 1], a[mi], &b[i][2]);
                }
        }
    };

    // ---- pipeline prologue ----
    prefetchL2(pfBase + 1 * (KC * 8));   // warm chunk 1 into L2
    prefetchL2(pfBase + 2 * (KC * 8));   // warm chunk 2 into L2
    stageA(0); CP_COMMIT();
    stageA(1); CP_COMMIT();
    ldgB(0, 0); stsB(0, 0);
    ldgB(0, 1); stsB(0, 1);
    CP_WAIT1();        // A(0) landed
    __syncthreads();

    // ---- main loop: R12 ordering + L2 prefetch of B two chunks ahead ----
    for (int c = 0; c < NCHUNK; ++c) {
        const bool more = (c + 1 < NCHUNK);
        if (c + 3 < NCHUNK)
            prefetchL2(pfBase + (size_t)(c + 3) * (KC * 8));   // B(c+3) -> L2
        if (more) ldgB(c + 1, 0);            // label A LDG (L2 hit), under ks0-1
        compute(c, 0, 2);
        if (more) { stsB(c + 1, 0); ldgB(c + 1, 1); }   // label B LDG under ks2-3
        compute(c, 2, 4);
        if (more) stsB(c + 1, 1);
        if (c + 2 < NCHUNK) { stageA(c + 2); CP_COMMIT(); }
        if (more) {
            if (c + 2 < NCHUNK) { CP_WAIT1(); } else { CP_WAIT0(); }
        }
        __syncthreads();
    }

    // ---- epilogue: relu(h + b1) . W2 + b2, quad-reduce over d ----
    const int gid = lane >> 2;
    const int tq  = lane & 3;
#pragma unroll
    for (int ni = 0; ni < 4; ++ni) {
        const int l = l0 + wn * 4 + ni;
        float2 bbv = *reinterpret_cast<const float2*>(b1 + (size_t)l * 8 + tq * 2);
        float2 wwv = *reinterpret_cast<const float2*>(W2 + (size_t)l * 8 + tq * 2);
        const float b2v = __ldg(b2 + l);
#pragma unroll
        for (int mi = 0; mi < 4; ++mi) {
            float s0 = fmaxf(acc[mi][ni][0] + bbv.x, 0.0f) * wwv.x
                     + fmaxf(acc[mi][ni][1] + bbv.y, 0.0f) * wwv.y;
            float s1 = fmaxf(acc[mi][ni][2] + bbv.x, 0.0f) * wwv.x
                     + fmaxf(acc[mi][ni][3] + bbv.y, 0.0f) * wwv.y;
            s0 += __shfl_xor_sync(0xffffffffu, s0, 1);
            s0 += __shfl_xor_sync(0xffffffffu, s0, 2);
            s1 += __shfl_xor_sync(0xffffffffu, s1, 1);
            s1 += __shfl_xor_sync(0xffffffffu, s1, 2);
            if (tq == 0) {
                const int b = m0 + wm * 64 + mi * 16 + gid;
                out[(size_t)b * L + l]       = s0 + b2v;
                out[(size_t)(b + 8) * L + l] = s1 + b2v;
            }
        }
    }
}

extern "C" void kernel_launch(void* const* d_in, const int* in_sizes, int n_in,
                              void* d_out, int out_size)
{
    const float* emb = (const float*)d_in[0];  // [B, H]
    const float* W1  = (const float*)d_in[1];  // [L, H, 8]
    const float* b1  = (const float*)d_in[2];  // [L, 8]
    const float* W2  = (const float*)d_in[3];  // [L, 8]
    const float* b2  = (const float*)d_in[4];  // [L]
    float* out       = (float*)d_out;          // [B, L]

    cudaFuncSetAttribute(imec_hmma_kernel,
                         cudaFuncAttributeMaxDynamicSharedMemorySize, SMEM_DYN);

    cvt_emb_kernel<<<BB * H / 4 / 256, 256>>>(emb);
    imec_hmma_kernel<<<(L / LPB) * 2, 256, SMEM_DYN>>>(W1, b1, W2, b2, out);
}

// round 14
// speedup vs baseline: 1.1148x; 1.1148x over previous
#include <cuda_runtime.h>
#include <cuda_fp16.h>
#include <cstdint>

// Problem constants
constexpr int BB = 256;     // batch
constexpr int H  = 1024;    // hidden
constexpr int L  = 10000;   // labels
constexpr int MT = 128;     // M per CTA
constexpr int LPB = 16;     // labels per CTA (N = 128)
constexpr int KC = 64;      // K per chunk
constexpr int NCHUNK = H / KC;  // 16
constexpr int NSTAGE_A = 3;

// smem: A 3 stages x 16KB, B 2 bufs x 16KB
constexpr int OFF_A = 0;
constexpr int A_STAGE = 16384;
constexpr int OFF_B = NSTAGE_A * A_STAGE;       // 49152
constexpr int B_BUF = 16384;
constexpr int SMEM_DYN = 1024 + OFF_B + 2 * B_BUF;   // 82944

// pre-converted fp16 embeddings [256][1024]
__device__ __align__(16) __half g_eA[BB * H];

// ---------------- helpers ----------------
__device__ __forceinline__ uint32_t smem_u32(const void* p) {
    uint32_t a;
    asm("{ .reg .u64 t; cvta.to.shared.u64 t, %1; cvt.u32.u64 %0, t; }" : "=r"(a) : "l"(p));
    return a;
}
__device__ __forceinline__ void cpasync16(uint32_t dst, const void* src) {
    asm volatile("cp.async.cg.shared.global [%0], [%1], 16;" :: "r"(dst), "l"(src));
}
#define CP_COMMIT() asm volatile("cp.async.commit_group;" ::: "memory")
#define CP_WAIT1()  asm volatile("cp.async.wait_group 1;" ::: "memory")
#define CP_WAIT0()  asm volatile("cp.async.wait_group 0;" ::: "memory")

__device__ __forceinline__ void ldsm4(uint32_t* r, uint32_t addr) {
    asm volatile("ldmatrix.sync.aligned.m8n8.x4.shared.b16 {%0,%1,%2,%3}, [%4];"
                 : "=r"(r[0]), "=r"(r[1]), "=r"(r[2]), "=r"(r[3]) : "r"(addr));
}
__device__ __forceinline__ void ldsm4t(uint32_t* r, uint32_t addr) {
    asm volatile("ldmatrix.sync.aligned.m8n8.x4.trans.shared.b16 {%0,%1,%2,%3}, [%4];"
                 : "=r"(r[0]), "=r"(r[1]), "=r"(r[2]), "=r"(r[3]) : "r"(addr));
}
__device__ __forceinline__ void mma16816(float* c, const uint32_t* a, const uint32_t* b) {
    asm volatile(
        "mma.sync.aligned.m16n8k16.row.col.f32.f16.f16.f32 "
        "{%0,%1,%2,%3}, {%4,%5,%6,%7}, {%8,%9}, {%0,%1,%2,%3};"
        : "+f"(c[0]), "+f"(c[1]), "+f"(c[2]), "+f"(c[3])
        : "r"(a[0]), "r"(a[1]), "r"(a[2]), "r"(a[3]), "r"(b[0]), "r"(b[1]));
}
__device__ __forceinline__ uint32_t pkh2(float x0, float x1) {
    __half2 h = __float22half2_rn(make_float2(x0, x1));
    return *reinterpret_cast<uint32_t*>(&h);
}

// ---------------- pre-kernel: emb fp32 -> fp16 ----------------
__global__ void cvt_emb_kernel(const float* __restrict__ emb) {
    int i = blockIdx.x * blockDim.x + threadIdx.x;   // 65536 float4s
    float4 v = reinterpret_cast<const float4*>(emb)[i];
    reinterpret_cast<uint2*>(g_eA)[i] = make_uint2(pkh2(v.x, v.y), pkh2(v.z, v.w));
}

// ---------------- main kernel ----------------
__global__ __launch_bounds__(256, 2)
void imec_hmma_kernel(const float* __restrict__ W1,
                      const float* __restrict__ b1,
                      const float* __restrict__ W2,
                      const float* __restrict__ b2,
                      float* __restrict__ out)
{
    extern __shared__ char smraw[];
    uint32_t sraw = smem_u32(smraw);
    uint32_t sb = (sraw + 1023u) & ~1023u;
    char* smc = smraw + (sb - sraw);

    const int tid  = threadIdx.x;
    const int lane = tid & 31;
    const int wid  = tid >> 5;        // 0..7
    const int wm   = wid & 1;         // warp M group: 64 rows each (2x64=128)
    const int wn   = wid >> 1;        // warp N group: 32 cols = 4 labels (4x32=128)

    const int lg = blockIdx.x >> 1;
    const int mt = blockIdx.x & 1;
    const int m0 = mt * MT;
    const int l0 = lg * LPB;

    // ---- A staging: thread -> (row, k-half), 128B swizzled rows ----
    const int ar = tid >> 1;          // 0..127
    const int ahalf = tid & 1;
    const char* aSrc = reinterpret_cast<const char*>(g_eA)
                     + (size_t)(m0 + ar) * (H * 2) + ahalf * 64;
    const uint32_t aDstBase = (uint32_t)(ar * 128);
    const uint32_t arx = (uint32_t)(ar & 7);

    // ---- B staging: warp owns 2 labels (2*wid, 2*wid+1); coalesced LDG.128 ----
    const float* bSrc0 = W1 + (size_t)(l0 + 2 * wid)     * (H * 8);
    const float* bSrc1 = W1 + (size_t)(l0 + 2 * wid + 1) * (H * 8);
    const uint32_t bDst0 = (uint32_t)((2 * wid)     * 1024) + (uint32_t)(lane * 8);
    const uint32_t bDst1 = (uint32_t)((2 * wid + 1) * 1024) + (uint32_t)(lane * 8);

    // ---- A fragment addresses (K-major, swizzled) ----
    uint32_t aOff[4], aXor[4];
#pragma unroll
    for (int mi = 0; mi < 4; ++mi) {
        int r = wm * 64 + mi * 16 + (lane & 15);
        aOff[mi] = (uint32_t)r * 128u;
        aXor[mi] = (uint32_t)(r & 7) << 4;
    }
    const uint32_t aKadd = (uint32_t)(lane >> 4) << 4;

    // ---- B fragment addresses (per-label 1KB MN-major blobs, trans ldsm) ----
    uint32_t bOff[2];
#pragma unroll
    for (int i = 0; i < 2; ++i)
        bOff[i] = (uint32_t)((wn * 4 + 2 * i + (lane >> 4)) * 1024 + (lane & 15) * 16);

    float acc[4][4][4];
#pragma unroll
    for (int mi = 0; mi < 4; ++mi)
#pragma unroll
        for (int ni = 0; ni < 4; ++ni)
#pragma unroll
            for (int k = 0; k < 4; ++k) acc[mi][ni][k] = 0.0f;

    float4 bv[4];   // B prefetch for ONE label (reused per half)

    auto stageA = [&](int c) {
        const uint32_t ad = sb + (uint32_t)(OFF_A + (c % NSTAGE_A) * A_STAGE) + aDstBase;
        const char* as = aSrc + c * 128;
#pragma unroll
        for (int j = 0; j < 4; ++j) {
            uint32_t u = (uint32_t)(ahalf * 4 + j);
            cpasync16(ad + ((u ^ arx) << 4), as + j * 16);
        }
    };

    auto ldgB = [&](int c, int h) {
        const float* s = (h == 0 ? bSrc0 : bSrc1) + (size_t)c * (KC * 8);
#pragma unroll
        for (int j = 0; j < 4; ++j)
            bv[j] = *reinterpret_cast<const float4*>(s + j * 128 + lane * 4);
    };

    auto stsB = [&](int c, int h) {
        char* bd = smc + OFF_B + (c & 1) * B_BUF + (h == 0 ? bDst0 : bDst1);
#pragma unroll
        for (int j = 0; j < 4; ++j) {
            uint2 w = make_uint2(pkh2(bv[j].x, bv[j].y), pkh2(bv[j].z, bv[j].w));
            *reinterpret_cast<uint2*>(bd + j * 256) = w;
        }
    };

    auto compute = [&](int c, int ks0, int ks1) {
        const uint32_t bA = sb + (uint32_t)(OFF_A + (c % NSTAGE_A) * A_STAGE);
        const uint32_t bB = sb + (uint32_t)(OFF_B + (c & 1) * B_BUF);
#pragma unroll
        for (int ks = ks0; ks < ks1; ++ks) {
            const uint32_t koff = (uint32_t)ks * 32u;
            uint32_t a[4][4], b[2][4];
#pragma unroll
            for (int mi = 0; mi < 4; ++mi)
                ldsm4(a[mi], bA + aOff[mi] + ((koff + aKadd) ^ aXor[mi]));
#pragma unroll
            for (int i = 0; i < 2; ++i)
                ldsm4t(b[i], bB + bOff[i] + (uint32_t)ks * 256u);
#pragma unroll
            for (int mi = 0; mi < 4; ++mi)
#pragma unroll
                for (int i = 0; i < 2; ++i) {
                    mma16816(acc[mi][2 * i],     a[mi], &b[i][0]);
                    mma16816(acc[mi][2 * i + 1], a[mi], &b[i][2]);
                }
        }
    };

    // ---- pipeline prologue ----
    stageA(0); CP_COMMIT();
    stageA(1); CP_COMMIT();
    ldgB(0, 0); stsB(0, 0);
    ldgB(0, 1); stsB(0, 1);
    CP_WAIT1();        // A(0) landed
    __syncthreads();

    // ---- main loop: R12 ordering (unchanged) ----
    for (int c = 0; c < NCHUNK; ++c) {
        const bool more = (c + 1 < NCHUNK);
        if (more) ldgB(c + 1, 0);            // label A LDG, hidden under ks0-1
        compute(c, 0, 2);
        if (more) { stsB(c + 1, 0); ldgB(c + 1, 1); }   // label B LDG under ks2-3
        compute(c, 2, 4);
        if (more) stsB(c + 1, 1);
        if (c + 2 < NCHUNK) { stageA(c + 2); CP_COMMIT(); }
        if (more) {
            if (c + 2 < NCHUNK) { CP_WAIT1(); } else { CP_WAIT0(); }
        }
        __syncthreads();
    }

    // ---- epilogue: relu(h + b1) . W2 + b2, quad-reduce, then COALESCED store ----
    // Stage the CTA's 128x16 fp32 output tile in smem (reuse A region),
    // row-padded to 20 words so STS is conflict-free and rows are float4-aligned.
    float* eTile = reinterpret_cast<float*>(smc);   // 128 * 20 * 4B = 10240 B
    const int gid = lane >> 2;
    const int tq  = lane & 3;
#pragma unroll
    for (int ni = 0; ni < 4; ++ni) {
        const int l = l0 + wn * 4 + ni;
        float2 bbv = *reinterpret_cast<const float2*>(b1 + (size_t)l * 8 + tq * 2);
        float2 wwv = *reinterpret_cast<const float2*>(W2 + (size_t)l * 8 + tq * 2);
        const float b2v = __ldg(b2 + l);
#pragma unroll
        for (int mi = 0; mi < 4; ++mi) {
            float s0 = fmaxf(acc[mi][ni][0] + bbv.x, 0.0f) * wwv.x
                     + fmaxf(acc[mi][ni][1] + bbv.y, 0.0f) * wwv.y;
            float s1 = fmaxf(acc[mi][ni][2] + bbv.x, 0.0f) * wwv.x
                     + fmaxf(acc[mi][ni][3] + bbv.y, 0.0f) * wwv.y;
            s0 += __shfl_xor_sync(0xffffffffu, s0, 1);
            s0 += __shfl_xor_sync(0xffffffffu, s0, 2);
            s1 += __shfl_xor_sync(0xffffffffu, s1, 1);
            s1 += __shfl_xor_sync(0xffffffffu, s1, 2);
            if (tq == 0) {
                const int r = wm * 64 + mi * 16 + gid;   // local row in [0,128)
                const int cc = wn * 4 + ni;              // local col in [0,16)
                eTile[r * 20 + cc]       = s0 + b2v;
                eTile[(r + 8) * 20 + cc] = s1 + b2v;
            }
        }
    }
    __syncthreads();

    // Coalesced flush: 512 float4 = 128 rows x 16 floats, 2 per thread.
#pragma unroll
    for (int i = tid; i < 512; i += 256) {
        const int r = i >> 2;
        const int q = i & 3;
        float4 v = *reinterpret_cast<const float4*>(&eTile[r * 20 + q * 4]);
        *reinterpret_cast<float4*>(out + (size_t)(m0 + r) * L + l0 + q * 4) = v;
    }
}

extern "C" void kernel_launch(void* const* d_in, const int* in_sizes, int n_in,
                              void* d_out, int out_size)
{
    const float* emb = (const float*)d_in[0];  // [B, H]
    const float* W1  = (const float*)d_in[1];  // [L, H, 8]
    const float* b1  = (const float*)d_in[2];  // [L, 8]
    const float* W2  = (const float*)d_in[3];  // [L, 8]
    const float* b2  = (const float*)d_in[4];  // [L]
    float* out       = (float*)d_out;          // [B, L]

    cudaFuncSetAttribute(imec_hmma_kernel,
                         cudaFuncAttributeMaxDynamicSharedMemorySize, SMEM_DYN);

    cvt_emb_kernel<<<BB * H / 4 / 256, 256>>>(emb);
    imec_hmma_kernel<<<(L / LPB) * 2, 256, SMEM_DYN>>>(W1, b1, W2, b2, out);
}